// round 11
// baseline (speedup 1.0000x reference)
#include <cuda_runtime.h>
#include <cuda_fp16.h>
#include <cstdint>

// ─────────────────────────────────────────────────────────────────────────────
// KPConv: prep (x→fp16, W transpose→fp16) ➜ producer with per-point HMMA
// phase 4; x-row gather via wide LDG.128/STS.128 software-pipelined across
// points ➜ fp16 HMMA GEMM, 8 warps/CTA (32x64 warp tiles), 4-stage ring.
// tcgen05 unavailable (harness PTX target is sm_103, not sm_103a).
// ─────────────────────────────────────────────────────────────────────────────

namespace {

typedef unsigned long long u64;

constexpr int H    = 26;
constexpr int KP   = 10;
constexpr int CIN  = 64;
constexpr int COUT = 128;
constexpr int KDIM = KP * CIN;   // 640
constexpr int TILE = 32;         // points per producer CTA
constexpr int NT   = 256;        // 8 warps
constexpr float INV_EXT = 1.0f / 1.2f;
constexpr int MAXN = 65536;

__device__ __half g_A[(size_t)MAXN * KDIM];
__device__ __half g_B[(size_t)COUT * KDIM];   // [o][k*64+i]
__device__ __half g_X[(size_t)MAXN * CIN];    // fp16 copy of x

__device__ __forceinline__ uint32_t smem_u32(const void* p) {
  uint32_t a;
  asm("{ .reg .u64 t; cvta.to.shared.u64 t, %1; cvt.u32.u64 %0, t; }"
      : "=r"(a) : "l"(p));
  return a;
}

__device__ __forceinline__ u64 ffma2(u64 a, u64 b, u64 c) {
  u64 d;
  asm("fma.rn.f32x2 %0, %1, %2, %3;" : "=l"(d) : "l"(a), "l"(b), "l"(c));
  return d;
}
__device__ __forceinline__ u64 pack2(float lo, float hi) {
  u64 d;
  asm("mov.b64 %0, {%1, %2};" : "=l"(d) : "f"(lo), "f"(hi));
  return d;
}
__device__ __forceinline__ float2 unpack2(u64 v) {
  float2 r;
  asm("mov.b64 {%0, %1}, %2;" : "=f"(r.x), "=f"(r.y) : "l"(v));
  return r;
}

__device__ __forceinline__ void cp16(uint32_t dst, const void* src) {
  asm volatile("cp.async.cg.shared.global [%0], [%1], 16;"
               :: "r"(dst), "l"(src) : "memory");
}
__device__ __forceinline__ void cp_commit() {
  asm volatile("cp.async.commit_group;" ::: "memory");
}
__device__ __forceinline__ void cp_wait2() {
  asm volatile("cp.async.wait_group 2;" ::: "memory");
}

__device__ __forceinline__ void ldm4(uint32_t* r, uint32_t addr) {
  asm volatile("ldmatrix.sync.aligned.m8n8.x4.shared.b16 {%0,%1,%2,%3}, [%4];"
               : "=r"(r[0]), "=r"(r[1]), "=r"(r[2]), "=r"(r[3]) : "r"(addr));
}
__device__ __forceinline__ void ldm4t(uint32_t* r, uint32_t addr) {
  asm volatile("ldmatrix.sync.aligned.m8n8.x4.trans.shared.b16 {%0,%1,%2,%3}, [%4];"
               : "=r"(r[0]), "=r"(r[1]), "=r"(r[2]), "=r"(r[3]) : "r"(addr));
}

__device__ __forceinline__ void mma16816(float* d, const uint32_t* a,
                                         const uint32_t* b) {
  asm volatile(
      "mma.sync.aligned.m16n8k16.row.col.f32.f16.f16.f32 "
      "{%0,%1,%2,%3}, {%4,%5,%6,%7}, {%8,%9}, {%0,%1,%2,%3};"
      : "+f"(d[0]), "+f"(d[1]), "+f"(d[2]), "+f"(d[3])
      : "r"(a[0]), "r"(a[1]), "r"(a[2]), "r"(a[3]), "r"(b[0]), "r"(b[1]));
}

// ───────────────────── Kernel 0: prep (x→fp16, W→fp16 transposed) ───────────────

__global__ void prep_kernel(const float* __restrict__ x,
                            const float* __restrict__ weights,
                            int total_x)
{
  const int gid    = blockIdx.x * blockDim.x + threadIdx.x;
  const int stride = gridDim.x * blockDim.x;

  const int nv = total_x / 4;
  const float4* xv = reinterpret_cast<const float4*>(x);
  for (int i = gid; i < nv; i += stride) {
    const float4 v = xv[i];
    __half2* dst = reinterpret_cast<__half2*>(g_X + (size_t)i * 4);
    dst[0] = __floats2half2_rn(v.x, v.y);
    dst[1] = __floats2half2_rn(v.z, v.w);
  }
  for (int t = gid; t < KDIM * COUT; t += stride) {
    const int o  = t / KDIM;
    const int ki = t - o * KDIM;
    g_B[t] = __float2half_rn(weights[(size_t)ki * COUT + o]);
  }
}

// ───────────────────── Kernel 1: producer (HMMA phase 4, wide gather) ───────────

struct PSmem {
  char  xT[8][32 * 128];        // per-warp x tile, XOR swizzled
  __half wT[8][16 * 40];        // per-warp weight tile (pitch 80 B)
  u64   genWT2[42 * 32];
  float genB[32];
  float sP[8][4][84];
  float sKP[8][4][32];
  int   sIdx[8][4][H];
};
constexpr int PSMEM = sizeof(PSmem);   // ~71 KB

__global__ void __launch_bounds__(NT, 3)
producer_kernel(const float* __restrict__ q_pts,
                const float* __restrict__ s_pts,
                const float* __restrict__ genW,
                const float* __restrict__ genB,
                const int*   __restrict__ inds,
                int N, int Ns)
{
  extern __shared__ char smraw[];
  PSmem& sm = *reinterpret_cast<PSmem*>(smraw);
  const int tid  = threadIdx.x;
  const int lane = tid & 31;
  const int wid  = tid >> 5;

  for (int t = tid; t < 42 * 32; t += NT) {
    const int j  = t & 31;
    const int m2 = t >> 5;
    sm.genWT2[t] = (j < 30)
        ? pack2(genW[j * 84 + 2 * m2], genW[j * 84 + 2 * m2 + 1]) : 0;
  }
  if (tid < 30) sm.genB[tid] = genB[tid];
  {
    uint4 z = make_uint4(0, 0, 0, 0);
    uint4* xz = reinterpret_cast<uint4*>(sm.xT);
    for (int t = tid; t < (8 * 32 * 128) / 16; t += NT) xz[t] = z;
    uint4* wz = reinterpret_cast<uint4*>(sm.wT);
    for (int t = tid; t < (8 * 16 * 80) / 16; t += NT) wz[t] = z;
  }
  __syncthreads();

  const int nw = blockIdx.x * TILE + wid * 4;

  // ── Phase 1 (batched 4 points). ──
  if (lane < H) {
    int jj[4];
    #pragma unroll
    for (int p = 0; p < 4; ++p) {
      const int n = nw + p;
      jj[p] = (n < N) ? inds[(size_t)n * H + lane] : 0;
    }
    float cx[4], cy[4], cz[4];
    #pragma unroll
    for (int p = 0; p < 4; ++p) {
      int j = jj[p];
      if (j >= 0 && j < Ns) {
        cx[p] = s_pts[3 * j + 0];
        cy[p] = s_pts[3 * j + 1];
        cz[p] = s_pts[3 * j + 2];
      } else {
        cx[p] = cy[p] = cz[p] = 1e6f;   // shadow point -> zero influence
        jj[p] = 0;
      }
    }
    #pragma unroll
    for (int p = 0; p < 4; ++p) {
      const int n = nw + p;
      float qx = 0.f, qy = 0.f, qz = 0.f;
      if (n < N) {
        qx = q_pts[3 * n + 0];
        qy = q_pts[3 * n + 1];
        qz = q_pts[3 * n + 2];
      }
      sm.sP[wid][p][lane * 3 + 0] = cx[p] - qx;
      sm.sP[wid][p][lane * 3 + 1] = cy[p] - qy;
      sm.sP[wid][p][lane * 3 + 2] = cz[p] - qz;
      sm.sIdx[wid][p][lane] = jj[p];
    }
  } else if (lane < 28) {
    const int b = lane - H;
    #pragma unroll
    for (int p = 0; p < 4; ++p) {
      sm.sP[wid][p][78 + b * 3 + 0] = -1.0f;
      sm.sP[wid][p][78 + b * 3 + 1] = -1.0f;
      sm.sP[wid][p][78 + b * 3 + 2] = -1.0f;
    }
  }
  __syncwarp();

  // ── Phase 2 (batched): kp = gen_W @ p_vec + gen_b. ──
  if (lane < 30) {
    u64 aA[4] = {0, 0, 0, 0}, aB[4] = {0, 0, 0, 0};
    const u64* pp0 = reinterpret_cast<const u64*>(&sm.sP[wid][0][0]);
    const u64* pp1 = reinterpret_cast<const u64*>(&sm.sP[wid][1][0]);
    const u64* pp2 = reinterpret_cast<const u64*>(&sm.sP[wid][2][0]);
    const u64* pp3 = reinterpret_cast<const u64*>(&sm.sP[wid][3][0]);
    #pragma unroll 7
    for (int m2 = 0; m2 < 21; ++m2) {
      const u64 wA = sm.genWT2[m2 * 32 + lane];
      const u64 wB = sm.genWT2[(m2 + 21) * 32 + lane];
      aA[0] = ffma2(wA, pp0[m2], aA[0]);  aB[0] = ffma2(wB, pp0[m2 + 21], aB[0]);
      aA[1] = ffma2(wA, pp1[m2], aA[1]);  aB[1] = ffma2(wB, pp1[m2 + 21], aB[1]);
      aA[2] = ffma2(wA, pp2[m2], aA[2]);  aB[2] = ffma2(wB, pp2[m2 + 21], aB[2]);
      aA[3] = ffma2(wA, pp3[m2], aA[3]);  aB[3] = ffma2(wB, pp3[m2 + 21], aB[3]);
    }
    const float gb = sm.genB[lane];
    #pragma unroll
    for (int p = 0; p < 4; ++p) {
      const float2 ra = unpack2(aA[p]);
      const float2 rb = unpack2(aB[p]);
      sm.sKP[wid][p][lane] = (ra.x + ra.y) + (rb.x + rb.y) + gb;
    }
  }
  __syncwarp();

  const uint32_t xb = smem_u32(&sm.xT[wid][0]);
  const uint32_t wb = smem_u32(&sm.wT[wid][0]);
  const int rr = lane >> 3;       // row slot within each LDG.128 warp-op
  const int cc = lane & 7;        // 16B chunk within row

  // Wide x-row gather into registers: 7 LDG.128 (26 rows x 128 B).
  uint4 v[7];
  auto load_x = [&](int p) {
    const int* idx = &sm.sIdx[wid][p][0];
    #pragma unroll
    for (int i = 0; i < 7; ++i) {
      const int r = i * 4 + rr;
      const int j = (r < H) ? idx[r] : 0;
      v[i] = *reinterpret_cast<const uint4*>(g_X + (size_t)j * CIN + cc * 8);
    }
  };
  load_x(0);   // point 0's gather in flight through phases below

  // ── Phases 3-4, software-pipelined across the 4 points. ──
  for (int p = 0; p < 4; ++p) {
    const int n = nw + p;

    __syncwarp();   // prior point's ldmatrix reads of wT/xT complete

    // Phase 3: w[k][h] fp16 into wT (overlaps in-flight LDG).
    for (int t = lane; t < KP * H; t += 32) {
      const int k = t / H;
      const int h = t - k * H;
      const float dx = sm.sP[wid][p][h * 3 + 0] - sm.sKP[wid][p][k * 3 + 0];
      const float dy = sm.sP[wid][p][h * 3 + 1] - sm.sKP[wid][p][k * 3 + 1];
      const float dz = sm.sP[wid][p][h * 3 + 2] - sm.sKP[wid][p][k * 3 + 2];
      const float d  = sqrtf(fmaf(dx, dx, fmaf(dy, dy, dz * dz)));
      sm.wT[wid][k * 40 + h] = __float2half(fmaxf(1.0f - d * INV_EXT, 0.0f));
    }

    // Store gathered rows to xT (consumes v; scoreboard waits if needed).
    #pragma unroll
    for (int i = 0; i < 7; ++i) {
      const int r = i * 4 + rr;
      if (r < H)
        *reinterpret_cast<uint4*>(
            sm.xT[wid] + r * 128 + ((cc * 16) ^ ((r & 7) << 4))) = v[i];
    }

    if (p < 3) load_x(p + 1);   // next point's gather overlaps mma below

    __syncwarp();

    // A frags from wT (16x32, pitch 80 — conflict-free).
    uint32_t a0[4], a1[4];
    const uint32_t aaddr = wb + (lane & 15) * 80 + ((lane >> 4) << 4);
    ldm4(a0, aaddr);
    ldm4(a1, aaddr + 32);

    float acc[8][4];
    #pragma unroll
    for (int j = 0; j < 8; ++j)
      #pragma unroll
      for (int q = 0; q < 4; ++q) acc[j][q] = 0.f;

    #pragma unroll
    for (int ks = 0; ks < 2; ++ks) {
      const uint32_t* ak = ks ? a1 : a0;
      #pragma unroll
      for (int nb = 0; nb < 4; ++nb) {
        const int kr = ks * 16 + (lane & 15);
        const uint32_t colB =
            (uint32_t)(nb * 32 + ((lane >> 4) << 4)) ^ ((kr & 7) << 4);
        uint32_t t4[4];
        ldm4t(t4, xb + kr * 128 + colB);
        mma16816(acc[2 * nb + 0], ak, t4);
        mma16816(acc[2 * nb + 1], ak, t4 + 2);
      }
    }

    if (n < N) {
      const int g  = lane >> 2;
      const int tc = (lane & 3) * 2;
      __half* base = g_A + (size_t)n * KDIM;
      #pragma unroll
      for (int j = 0; j < 8; ++j) {
        const int col = j * 8 + tc;
        *reinterpret_cast<__half2*>(base + g * 64 + col) =
            __floats2half2_rn(acc[j][0], acc[j][1]);
        if (g < 2)
          *reinterpret_cast<__half2*>(base + (g + 8) * 64 + col) =
              __floats2half2_rn(acc[j][2], acc[j][3]);
      }
    }
  }
}

// ───────────────────── Kernel 2: fp16 mma.sync GEMM out = A @ B^T ───────────────
// CTA 128x128, 8 warps in 4x2 grid of 32x64 tiles, 4-stage cp.async ring,
// 80B pitch. 2 CTAs/SM (16 warps for latency hiding).

constexpr int KT      = 32;
constexpr int PITCH   = 80;
constexpr int TSZ     = 128 * PITCH;
constexpr int STAGE   = 2 * TSZ;
constexpr int NSTAGES = 4;
constexpr int GSMEM   = NSTAGES * STAGE;   // 81920 B
constexpr int NKT     = KDIM / KT;         // 20
constexpr int GNT     = 256;               // 8 warps

__global__ void __launch_bounds__(GNT, 2)
gemm_kernel(float* __restrict__ out, int N)
{
  extern __shared__ char sm[];
  const uint32_t sb = smem_u32(sm);
  const int tid  = threadIdx.x;
  const int lane = tid & 31;
  const int wid  = tid >> 5;
  const int wr   = wid >> 1;       // 0..3 -> rows wr*32
  const int wc   = wid & 1;        // 0..1 -> cols wc*64
  const size_t n0 = (size_t)blockIdx.x * 128;

  const int id0 = tid, id1 = tid + 256;
  const int r0 = id0 >> 2, c0 = id0 & 3;
  const int r1 = id1 >> 2, c1 = id1 & 3;

  auto load_stage = [&](int st, int kc) {
    const uint32_t base = sb + st * STAGE;
    const uint32_t d0 = r0 * PITCH + c0 * 16;
    const uint32_t d1 = r1 * PITCH + c1 * 16;
    cp16(base + 0 * TSZ + d0, g_A + (n0 + r0) * KDIM + kc * KT + c0 * 8);
    cp16(base + 0 * TSZ + d1, g_A + (n0 + r1) * KDIM + kc * KT + c1 * 8);
    cp16(base + 1 * TSZ + d0, g_B + (size_t)r0 * KDIM + kc * KT + c0 * 8);
    cp16(base + 1 * TSZ + d1, g_B + (size_t)r1 * KDIM + kc * KT + c1 * 8);
  };

  load_stage(0, 0); cp_commit();
  load_stage(1, 1); cp_commit();
  load_stage(2, 2); cp_commit();

  const int arow  = lane & 15;
  const int acolB = (lane >> 4) * 16;
  const int brow  = (lane & 7) + ((lane >> 4) << 3);
  const int bcolB = ((lane >> 3) & 1) * 16;

  float acc[2][8][4];
  #pragma unroll
  for (int mi = 0; mi < 2; ++mi)
    #pragma unroll
    for (int ni = 0; ni < 8; ++ni)
      #pragma unroll
      for (int j = 0; j < 4; ++j) acc[mi][ni][j] = 0.f;

  for (int kc = 0; kc < NKT; ++kc) {
    const int st = kc & (NSTAGES - 1);
    cp_wait2();
    __syncthreads();

    if (kc + 3 < NKT) load_stage((kc + 3) & (NSTAGES - 1), kc + 3);
    cp_commit();

    const uint32_t tA = sb + st * STAGE + 0 * TSZ;
    const uint32_t tB = sb + st * STAGE + 1 * TSZ;

    #pragma unroll
    for (int ks = 0; ks < 2; ++ks) {
      uint32_t ah[2][4], bh[8][2];
      #pragma unroll
      for (int mi = 0; mi < 2; ++mi) {
        const uint32_t ao = (wr * 32 + mi * 16 + arow) * PITCH + ks * 32 + acolB;
        ldm4(ah[mi], tA + ao);
      }
      #pragma unroll
      for (int bi = 0; bi < 4; ++bi) {
        const uint32_t bo = (wc * 64 + bi * 16 + brow) * PITCH + ks * 32 + bcolB;
        uint32_t t4[4];
        ldm4(t4, tB + bo);
        bh[2 * bi][0] = t4[0]; bh[2 * bi][1] = t4[1];
        bh[2 * bi + 1][0] = t4[2]; bh[2 * bi + 1][1] = t4[3];
      }
      #pragma unroll
      for (int mi = 0; mi < 2; ++mi)
        #pragma unroll
        for (int ni = 0; ni < 8; ++ni)
          mma16816(acc[mi][ni], ah[mi], bh[ni]);
    }
  }

  const int trow = lane >> 2;
  const int tcol = (lane & 3) * 2;
  #pragma unroll
  for (int mi = 0; mi < 2; ++mi) {
    const size_t row = n0 + wr * 32 + mi * 16 + trow;
    #pragma unroll
    for (int ni = 0; ni < 8; ++ni) {
      const int col = wc * 64 + ni * 8 + tcol;
      if (row < (size_t)N) {
        *reinterpret_cast<float2*>(out + row * COUT + col) =
            make_float2(acc[mi][ni][0], acc[mi][ni][1]);
        *reinterpret_cast<float2*>(out + (row + 8) * COUT + col) =
            make_float2(acc[mi][ni][2], acc[mi][ni][3]);
      }
    }
  }
}

}  // namespace

// ───────────────────────────── launch ─────────────────────────────

extern "C" void kernel_launch(void* const* d_in, const int* in_sizes, int n_in,
                              void* d_out, int out_size) {
  const float* q_pts = (const float*)d_in[0];
  const float* s_pts = (const float*)d_in[1];
  const float* x     = (const float*)d_in[2];
  const float* genW  = (const float*)d_in[3];
  const float* genB  = (const float*)d_in[4];
  const float* wts   = (const float*)d_in[5];
  const int*   inds  = (const int*)d_in[6];
  float* out = (float*)d_out;

  int N  = in_sizes[0] / 3;
  const int Ns = in_sizes[1] / 3;
  if (N > MAXN) N = MAXN;

  cudaFuncSetAttribute(producer_kernel,
                       cudaFuncAttributeMaxDynamicSharedMemorySize, PSMEM);
  cudaFuncSetAttribute(gemm_kernel,
                       cudaFuncAttributeMaxDynamicSharedMemorySize, GSMEM);

  prep_kernel<<<1024, 256>>>(x, wts, N * CIN);

  const int grid1 = (N + TILE - 1) / TILE;
  producer_kernel<<<grid1, NT, PSMEM>>>(q_pts, s_pts, genW, genB, inds, N, Ns);

  const int grid3 = (N + 127) / 128;
  gemm_kernel<<<grid3, GNT, GSMEM>>>(out, N);
}

// round 12
// speedup vs baseline: 1.1087x; 1.1087x over previous
#include <cuda_runtime.h>
#include <cuda_fp16.h>
#include <cstdint>

// ─────────────────────────────────────────────────────────────────────────────
// KPConv: prep (x→fp16, W transpose→fp16) ➜ producer (round-8: batched
// phases 1-2, MLP-batched FFMA2 phase 4) ➜ fp16 HMMA GEMM with 64x64 warp
// tiles, KT=64 K-tiles, 3-stage cp.async ring (one sync per 64-K tile).
// tcgen05 unavailable (harness PTX target is sm_103, not sm_103a).
// ─────────────────────────────────────────────────────────────────────────────

namespace {

typedef unsigned long long u64;

constexpr int H    = 26;
constexpr int KP   = 10;
constexpr int CIN  = 64;
constexpr int COUT = 128;
constexpr int KDIM = KP * CIN;   // 640
constexpr int TILE = 32;
constexpr int NT   = 256;
constexpr float INV_EXT = 1.0f / 1.2f;
constexpr int MAXN = 65536;

__device__ __half g_A[(size_t)MAXN * KDIM];
__device__ __half g_B[(size_t)COUT * KDIM];   // [o][k*64+i]
__device__ __half g_X[(size_t)MAXN * CIN];    // fp16 copy of x

__device__ __forceinline__ uint32_t smem_u32(const void* p) {
  uint32_t a;
  asm("{ .reg .u64 t; cvta.to.shared.u64 t, %1; cvt.u32.u64 %0, t; }"
      : "=r"(a) : "l"(p));
  return a;
}

__device__ __forceinline__ u64 ffma2(u64 a, u64 b, u64 c) {
  u64 d;
  asm("fma.rn.f32x2 %0, %1, %2, %3;" : "=l"(d) : "l"(a), "l"(b), "l"(c));
  return d;
}
__device__ __forceinline__ u64 pack2(float lo, float hi) {
  u64 d;
  asm("mov.b64 %0, {%1, %2};" : "=l"(d) : "f"(lo), "f"(hi));
  return d;
}
__device__ __forceinline__ float2 unpack2(u64 v) {
  float2 r;
  asm("mov.b64 {%0, %1}, %2;" : "=f"(r.x), "=f"(r.y) : "l"(v));
  return r;
}

__device__ __forceinline__ void cp16(uint32_t dst, const void* src) {
  asm volatile("cp.async.cg.shared.global [%0], [%1], 16;"
               :: "r"(dst), "l"(src) : "memory");
}
__device__ __forceinline__ void cp_commit() {
  asm volatile("cp.async.commit_group;" ::: "memory");
}
__device__ __forceinline__ void cp_wait1() {
  asm volatile("cp.async.wait_group 1;" ::: "memory");
}

__device__ __forceinline__ void ldm4(uint32_t* r, uint32_t addr) {
  asm volatile("ldmatrix.sync.aligned.m8n8.x4.shared.b16 {%0,%1,%2,%3}, [%4];"
               : "=r"(r[0]), "=r"(r[1]), "=r"(r[2]), "=r"(r[3]) : "r"(addr));
}

__device__ __forceinline__ void mma16816(float* d, const uint32_t* a,
                                         const uint32_t* b) {
  asm volatile(
      "mma.sync.aligned.m16n8k16.row.col.f32.f16.f16.f32 "
      "{%0,%1,%2,%3}, {%4,%5,%6,%7}, {%8,%9}, {%0,%1,%2,%3};"
      : "+f"(d[0]), "+f"(d[1]), "+f"(d[2]), "+f"(d[3])
      : "r"(a[0]), "r"(a[1]), "r"(a[2]), "r"(a[3]), "r"(b[0]), "r"(b[1]));
}

// ───────────────────── Kernel 0: prep (x→fp16, W→fp16 transposed) ───────────────

__global__ void prep_kernel(const float* __restrict__ x,
                            const float* __restrict__ weights,
                            int total_x)
{
  const int gid    = blockIdx.x * blockDim.x + threadIdx.x;
  const int stride = gridDim.x * blockDim.x;

  const int nv = total_x / 4;
  const float4* xv = reinterpret_cast<const float4*>(x);
  for (int i = gid; i < nv; i += stride) {
    const float4 v = xv[i];
    __half2* dst = reinterpret_cast<__half2*>(g_X + (size_t)i * 4);
    dst[0] = __floats2half2_rn(v.x, v.y);
    dst[1] = __floats2half2_rn(v.z, v.w);
  }
  for (int t = gid; t < KDIM * COUT; t += stride) {
    const int o  = t / KDIM;
    const int ki = t - o * KDIM;
    g_B[t] = __float2half_rn(weights[(size_t)ki * COUT + o]);
  }
}

// ───────────────────── Kernel 1: producer (round-8 version, verbatim) ───────────

struct P1Smem {
  u64   genWT2[42 * 32];
  float genB[32];
  float sP[8][4][84];
  float sKP[8][4][32];
  alignas(16) float swv[8][H * 12];
  int   sIdx[8][4][H];
};

__global__ void __launch_bounds__(NT, 4)
producer_kernel(const float* __restrict__ q_pts,
                const float* __restrict__ s_pts,
                const float* __restrict__ genW,
                const float* __restrict__ genB,
                const int*   __restrict__ inds,
                int N, int Ns)
{
  __shared__ P1Smem sm;
  const int tid  = threadIdx.x;
  const int lane = tid & 31;
  const int wid  = tid >> 5;

  for (int t = tid; t < 42 * 32; t += NT) {
    const int j  = t & 31;
    const int m2 = t >> 5;
    sm.genWT2[t] = (j < 30)
        ? pack2(genW[j * 84 + 2 * m2], genW[j * 84 + 2 * m2 + 1]) : 0;
  }
  if (tid < 30) sm.genB[tid] = genB[tid];
  __syncthreads();

  const int nw = blockIdx.x * TILE + wid * 4;

  // Phase 1 (batched 4 points).
  if (lane < H) {
    int jj[4];
    #pragma unroll
    for (int p = 0; p < 4; ++p) {
      const int n = nw + p;
      jj[p] = (n < N) ? inds[(size_t)n * H + lane] : 0;
    }
    float cx[4], cy[4], cz[4];
    #pragma unroll
    for (int p = 0; p < 4; ++p) {
      int j = jj[p];
      if (j >= 0 && j < Ns) {
        cx[p] = s_pts[3 * j + 0];
        cy[p] = s_pts[3 * j + 1];
        cz[p] = s_pts[3 * j + 2];
      } else {
        cx[p] = cy[p] = cz[p] = 1e6f;
        jj[p] = 0;
      }
    }
    #pragma unroll
    for (int p = 0; p < 4; ++p) {
      const int n = nw + p;
      if (n < N) {
        const float qx = q_pts[3 * n + 0];
        const float qy = q_pts[3 * n + 1];
        const float qz = q_pts[3 * n + 2];
        sm.sP[wid][p][lane * 3 + 0] = cx[p] - qx;
        sm.sP[wid][p][lane * 3 + 1] = cy[p] - qy;
        sm.sP[wid][p][lane * 3 + 2] = cz[p] - qz;
        sm.sIdx[wid][p][lane] = jj[p];
      }
    }
  } else if (lane < 28) {
    const int b = lane - H;
    #pragma unroll
    for (int p = 0; p < 4; ++p) {
      sm.sP[wid][p][78 + b * 3 + 0] = -1.0f;
      sm.sP[wid][p][78 + b * 3 + 1] = -1.0f;
      sm.sP[wid][p][78 + b * 3 + 2] = -1.0f;
    }
  }
  __syncwarp();

  // Phase 2 (batched): kp = gen_W @ p_vec + gen_b.
  if (lane < 30) {
    u64 aA[4] = {0, 0, 0, 0}, aB[4] = {0, 0, 0, 0};
    const u64* pp0 = reinterpret_cast<const u64*>(&sm.sP[wid][0][0]);
    const u64* pp1 = reinterpret_cast<const u64*>(&sm.sP[wid][1][0]);
    const u64* pp2 = reinterpret_cast<const u64*>(&sm.sP[wid][2][0]);
    const u64* pp3 = reinterpret_cast<const u64*>(&sm.sP[wid][3][0]);
    #pragma unroll 7
    for (int m2 = 0; m2 < 21; ++m2) {
      const u64 wA = sm.genWT2[m2 * 32 + lane];
      const u64 wB = sm.genWT2[(m2 + 21) * 32 + lane];
      aA[0] = ffma2(wA, pp0[m2], aA[0]);  aB[0] = ffma2(wB, pp0[m2 + 21], aB[0]);
      aA[1] = ffma2(wA, pp1[m2], aA[1]);  aB[1] = ffma2(wB, pp1[m2 + 21], aB[1]);
      aA[2] = ffma2(wA, pp2[m2], aA[2]);  aB[2] = ffma2(wB, pp2[m2 + 21], aB[2]);
      aA[3] = ffma2(wA, pp3[m2], aA[3]);  aB[3] = ffma2(wB, pp3[m2 + 21], aB[3]);
    }
    const float gb = sm.genB[lane];
    #pragma unroll
    for (int p = 0; p < 4; ++p) {
      const float2 ra = unpack2(aA[p]);
      const float2 rb = unpack2(aB[p]);
      sm.sKP[wid][p][lane] = (ra.x + ra.y) + (rb.x + rb.y) + gb;
    }
  }
  __syncwarp();

  // Phases 3-4 per point.
  for (int p = 0; p < 4; ++p) {
    const int n = nw + p;
    if (n >= N) continue;

    const int* idx = &sm.sIdx[wid][p][0];

    __half2 xb[9];
    #pragma unroll
    for (int hh = 0; hh < 9; ++hh)
      xb[hh] = *reinterpret_cast<const __half2*>(
          g_X + (size_t)idx[hh] * CIN + 2 * lane);

    __syncwarp();

    for (int t = lane; t < KP * H; t += 32) {
      const int k = t / H;
      const int h = t - k * H;
      const float dx = sm.sP[wid][p][h * 3 + 0] - sm.sKP[wid][p][k * 3 + 0];
      const float dy = sm.sP[wid][p][h * 3 + 1] - sm.sKP[wid][p][k * 3 + 1];
      const float dz = sm.sP[wid][p][h * 3 + 2] - sm.sKP[wid][p][k * 3 + 2];
      const float d  = sqrtf(fmaf(dx, dx, fmaf(dy, dy, dz * dz)));
      sm.swv[wid][h * 12 + k] = fmaxf(1.0f - d * INV_EXT, 0.0f);
    }
    __syncwarp();

    u64 acc2[5][2];
    #pragma unroll
    for (int kk = 0; kk < 5; ++kk) { acc2[kk][0] = 0; acc2[kk][1] = 0; }

    auto accum = [&](int h, __half2 xh) {
      const float2 xv = __half22float2(xh);
      const u64 x0 = pack2(xv.x, xv.x);
      const u64 x1 = pack2(xv.y, xv.y);
      const u64* wp = reinterpret_cast<const u64*>(&sm.swv[wid][h * 12]);
      #pragma unroll
      for (int kk = 0; kk < 5; ++kk) {
        const u64 w2 = wp[kk];
        acc2[kk][0] = ffma2(w2, x0, acc2[kk][0]);
        acc2[kk][1] = ffma2(w2, x1, acc2[kk][1]);
      }
    };

    __half2 xc[9];
    #pragma unroll
    for (int hh = 0; hh < 9; ++hh)
      xc[hh] = *reinterpret_cast<const __half2*>(
          g_X + (size_t)idx[9 + hh] * CIN + 2 * lane);
    #pragma unroll
    for (int hh = 0; hh < 9; ++hh) accum(hh, xb[hh]);

    #pragma unroll
    for (int hh = 0; hh < 8; ++hh)
      xb[hh] = *reinterpret_cast<const __half2*>(
          g_X + (size_t)idx[18 + hh] * CIN + 2 * lane);
    #pragma unroll
    for (int hh = 0; hh < 9; ++hh) accum(9 + hh, xc[hh]);
    #pragma unroll
    for (int hh = 0; hh < 8; ++hh) accum(18 + hh, xb[hh]);

    #pragma unroll
    for (int kk = 0; kk < 5; ++kk) {
      const float2 a0 = unpack2(acc2[kk][0]);
      const float2 a1 = unpack2(acc2[kk][1]);
      const size_t off0 = (size_t)n * KDIM + (2 * kk) * CIN + 2 * lane;
      const size_t off1 = (size_t)n * KDIM + (2 * kk + 1) * CIN + 2 * lane;
      *reinterpret_cast<__half2*>(g_A + off0) = __floats2half2_rn(a0.x, a1.x);
      *reinterpret_cast<__half2*>(g_A + off1) = __floats2half2_rn(a0.y, a1.y);
    }
    __syncwarp();
  }
}

// ───────────────────── Kernel 2: fp16 mma.sync GEMM out = A @ B^T ───────────────
// CTA 128x128, 4 warps in 2x2 grid of 64x64 tiles (16 MAC/B). KT=64 K-tiles
// (10 total), 3-stage cp.async ring — ONE __syncthreads per 64-K tile.
// Pitch 144 B (36 words; 8-row phases hit banks {0,4,...,28} — conflict-free).

constexpr int KT      = 64;
constexpr int PITCH   = 144;
constexpr int TSZ     = 128 * PITCH;       // 18432 B
constexpr int STAGE   = 2 * TSZ;           // A + B = 36864 B
constexpr int NSTAGES = 3;
constexpr int GSMEM   = NSTAGES * STAGE;   // 110592 B (2 CTA/SM = 216 KB)
constexpr int NKT     = KDIM / KT;         // 10
constexpr int GNT     = 128;               // 4 warps

__global__ void __launch_bounds__(GNT, 2)
gemm_kernel(float* __restrict__ out, int N)
{
  extern __shared__ char sm[];
  const uint32_t sb = smem_u32(sm);
  const int tid  = threadIdx.x;
  const int lane = tid & 31;
  const int wid  = tid >> 5;
  const int wr   = wid >> 1;       // 0..1 -> rows wr*64
  const int wc   = wid & 1;        // 0..1 -> cols wc*64
  const size_t n0 = (size_t)blockIdx.x * 128;

  // Stage = 128 rows x 8 chunks of 16B per matrix; 8 chunks/thread/matrix.
  auto load_stage = [&](int st, int kc) {
    const uint32_t base = sb + st * STAGE;
    #pragma unroll
    for (int i = 0; i < 8; ++i) {
      const int id = tid + i * GNT;
      const int r  = id >> 3;
      const int c  = id & 7;
      const uint32_t d = r * PITCH + c * 16;
      cp16(base + d,       g_A + (n0 + r) * KDIM + kc * KT + c * 8);
      cp16(base + TSZ + d, g_B + (size_t)r * KDIM + kc * KT + c * 8);
    }
  };

  load_stage(0, 0); cp_commit();
  load_stage(1, 1); cp_commit();

  const int arow  = lane & 15;
  const int acolB = (lane >> 4) * 16;
  const int brow  = (lane & 7) + ((lane >> 4) << 3);
  const int bcolB = ((lane >> 3) & 1) * 16;

  float acc[4][8][4];
  #pragma unroll
  for (int mi = 0; mi < 4; ++mi)
    #pragma unroll
    for (int ni = 0; ni < 8; ++ni)
      #pragma unroll
      for (int j = 0; j < 4; ++j) acc[mi][ni][j] = 0.f;

  for (int kc = 0; kc < NKT; ++kc) {
    const int st = kc % NSTAGES;
    cp_wait1();        // stage kc resident (only kc+1 may be pending)
    __syncthreads();   // everyone past tile kc-1 -> its slot is reusable

    if (kc + 2 < NKT) load_stage((kc + 2) % NSTAGES, kc + 2);
    cp_commit();

    const uint32_t tA = sb + st * STAGE;
    const uint32_t tB = sb + st * STAGE + TSZ;

    #pragma unroll
    for (int ks = 0; ks < 4; ++ks) {
      uint32_t ah[4][4], bh[8][2];
      #pragma unroll
      for (int mi = 0; mi < 4; ++mi) {
        const uint32_t ao =
            (wr * 64 + mi * 16 + arow) * PITCH + ks * 32 + acolB;
        ldm4(ah[mi], tA + ao);
      }
      #pragma unroll
      for (int bi = 0; bi < 4; ++bi) {
        const uint32_t bo =
            (wc * 64 + bi * 16 + brow) * PITCH + ks * 32 + bcolB;
        uint32_t t4[4];
        ldm4(t4, tB + bo);
        bh[2 * bi][0] = t4[0]; bh[2 * bi][1] = t4[1];
        bh[2 * bi + 1][0] = t4[2]; bh[2 * bi + 1][1] = t4[3];
      }
      #pragma unroll
      for (int mi = 0; mi < 4; ++mi)
        #pragma unroll
        for (int ni = 0; ni < 8; ++ni)
          mma16816(acc[mi][ni], ah[mi], bh[ni]);
    }
  }

  const int trow = lane >> 2;
  const int tcol = (lane & 3) * 2;
  #pragma unroll
  for (int mi = 0; mi < 4; ++mi) {
    const size_t row = n0 + wr * 64 + mi * 16 + trow;
    #pragma unroll
    for (int ni = 0; ni < 8; ++ni) {
      const int col = wc * 64 + ni * 8 + tcol;
      if (row < (size_t)N) {
        *reinterpret_cast<float2*>(out + row * COUT + col) =
            make_float2(acc[mi][ni][0], acc[mi][ni][1]);
        *reinterpret_cast<float2*>(out + (row + 8) * COUT + col) =
            make_float2(acc[mi][ni][2], acc[mi][ni][3]);
      }
    }
  }
}

}  // namespace

// ───────────────────────────── launch ─────────────────────────────

extern "C" void kernel_launch(void* const* d_in, const int* in_sizes, int n_in,
                              void* d_out, int out_size) {
  const float* q_pts = (const float*)d_in[0];
  const float* s_pts = (const float*)d_in[1];
  const float* x     = (const float*)d_in[2];
  const float* genW  = (const float*)d_in[3];
  const float* genB  = (const float*)d_in[4];
  const float* wts   = (const float*)d_in[5];
  const int*   inds  = (const int*)d_in[6];
  float* out = (float*)d_out;

  int N  = in_sizes[0] / 3;
  const int Ns = in_sizes[1] / 3;
  if (N > MAXN) N = MAXN;

  cudaFuncSetAttribute(gemm_kernel,
                       cudaFuncAttributeMaxDynamicSharedMemorySize, GSMEM);

  prep_kernel<<<1024, 256>>>(x, wts, N * CIN);

  const int grid1 = (N + TILE - 1) / TILE;
  producer_kernel<<<grid1, NT>>>(q_pts, s_pts, genW, genB, inds, N, Ns);

  const int grid3 = (N + 127) / 128;
  gemm_kernel<<<grid3, GNT, GSMEM>>>(out, N);
}

// round 13
// speedup vs baseline: 1.1491x; 1.0364x over previous
#include <cuda_runtime.h>
#include <cuda_fp16.h>
#include <cstdint>

// ─────────────────────────────────────────────────────────────────────────────
// KPConv: prep (x→fp16, W transpose→fp16) ➜ producer with PAIRED phase 4:
// lanes 0-15 own point p0, lanes 16-31 own p1, so each LDG.64/LDS.64 serves
// two points (halves L1tex wavefront traffic — the measured producer bound)
// ➜ fp16 HMMA GEMM, 64x64 warp tiles, KT=64, 3-stage cp.async ring.
// tcgen05 unavailable (harness PTX target is sm_103, not sm_103a).
// ─────────────────────────────────────────────────────────────────────────────

namespace {

typedef unsigned long long u64;

constexpr int H    = 26;
constexpr int KP   = 10;
constexpr int CIN  = 64;
constexpr int COUT = 128;
constexpr int KDIM = KP * CIN;   // 640
constexpr int TILE = 32;
constexpr int NT   = 256;
constexpr float INV_EXT = 1.0f / 1.2f;
constexpr int MAXN = 65536;

__device__ __half g_A[(size_t)MAXN * KDIM];
__device__ __half g_B[(size_t)COUT * KDIM];   // [o][k*64+i]
__device__ __half g_X[(size_t)MAXN * CIN];    // fp16 copy of x

__device__ __forceinline__ uint32_t smem_u32(const void* p) {
  uint32_t a;
  asm("{ .reg .u64 t; cvta.to.shared.u64 t, %1; cvt.u32.u64 %0, t; }"
      : "=r"(a) : "l"(p));
  return a;
}

__device__ __forceinline__ u64 ffma2(u64 a, u64 b, u64 c) {
  u64 d;
  asm("fma.rn.f32x2 %0, %1, %2, %3;" : "=l"(d) : "l"(a), "l"(b), "l"(c));
  return d;
}
__device__ __forceinline__ u64 pack2(float lo, float hi) {
  u64 d;
  asm("mov.b64 %0, {%1, %2};" : "=l"(d) : "f"(lo), "f"(hi));
  return d;
}
__device__ __forceinline__ float2 unpack2(u64 v) {
  float2 r;
  asm("mov.b64 {%0, %1}, %2;" : "=f"(r.x), "=f"(r.y) : "l"(v));
  return r;
}

__device__ __forceinline__ void cp16(uint32_t dst, const void* src) {
  asm volatile("cp.async.cg.shared.global [%0], [%1], 16;"
               :: "r"(dst), "l"(src) : "memory");
}
__device__ __forceinline__ void cp_commit() {
  asm volatile("cp.async.commit_group;" ::: "memory");
}
__device__ __forceinline__ void cp_wait1() {
  asm volatile("cp.async.wait_group 1;" ::: "memory");
}

__device__ __forceinline__ void ldm4(uint32_t* r, uint32_t addr) {
  asm volatile("ldmatrix.sync.aligned.m8n8.x4.shared.b16 {%0,%1,%2,%3}, [%4];"
               : "=r"(r[0]), "=r"(r[1]), "=r"(r[2]), "=r"(r[3]) : "r"(addr));
}

__device__ __forceinline__ void mma16816(float* d, const uint32_t* a,
                                         const uint32_t* b) {
  asm volatile(
      "mma.sync.aligned.m16n8k16.row.col.f32.f16.f16.f32 "
      "{%0,%1,%2,%3}, {%4,%5,%6,%7}, {%8,%9}, {%0,%1,%2,%3};"
      : "+f"(d[0]), "+f"(d[1]), "+f"(d[2]), "+f"(d[3])
      : "r"(a[0]), "r"(a[1]), "r"(a[2]), "r"(a[3]), "r"(b[0]), "r"(b[1]));
}

// ───────────────────── Kernel 0: prep (x→fp16, W→fp16 transposed) ───────────────

__global__ void prep_kernel(const float* __restrict__ x,
                            const float* __restrict__ weights,
                            int total_x)
{
  const int gid    = blockIdx.x * blockDim.x + threadIdx.x;
  const int stride = gridDim.x * blockDim.x;

  const int nv = total_x / 4;
  const float4* xv = reinterpret_cast<const float4*>(x);
  for (int i = gid; i < nv; i += stride) {
    const float4 v = xv[i];
    __half2* dst = reinterpret_cast<__half2*>(g_X + (size_t)i * 4);
    dst[0] = __floats2half2_rn(v.x, v.y);
    dst[1] = __floats2half2_rn(v.z, v.w);
  }
  for (int t = gid; t < KDIM * COUT; t += stride) {
    const int o  = t / KDIM;
    const int ki = t - o * KDIM;
    g_B[t] = __float2half_rn(weights[(size_t)ki * COUT + o]);
  }
}

// ───────────────────── Kernel 1: producer (paired phase 4) ─────────────────────

struct P1Smem {
  u64   genWT2[42 * 32];
  float genB[32];
  float sP[8][4][84];
  float sKP[8][4][32];
  alignas(16) float swv[8][2][H * 12];   // per pair: [pt][h][k], stride 12
  int   sIdx[8][4][H];
};

__global__ void __launch_bounds__(NT, 3)
producer_kernel(const float* __restrict__ q_pts,
                const float* __restrict__ s_pts,
                const float* __restrict__ genW,
                const float* __restrict__ genB,
                const int*   __restrict__ inds,
                int N, int Ns)
{
  __shared__ P1Smem sm;
  const int tid  = threadIdx.x;
  const int lane = tid & 31;
  const int wid  = tid >> 5;

  for (int t = tid; t < 42 * 32; t += NT) {
    const int j  = t & 31;
    const int m2 = t >> 5;
    sm.genWT2[t] = (j < 30)
        ? pack2(genW[j * 84 + 2 * m2], genW[j * 84 + 2 * m2 + 1]) : 0;
  }
  if (tid < 30) sm.genB[tid] = genB[tid];
  __syncthreads();

  const int nw = blockIdx.x * TILE + wid * 4;

  // ── Phase 1 (batched 4 points); sP/sIdx always written (safe fallbacks). ──
  if (lane < H) {
    int jj[4];
    #pragma unroll
    for (int p = 0; p < 4; ++p) {
      const int n = nw + p;
      jj[p] = (n < N) ? inds[(size_t)n * H + lane] : 0;
    }
    float cx[4], cy[4], cz[4];
    #pragma unroll
    for (int p = 0; p < 4; ++p) {
      int j = jj[p];
      if (j >= 0 && j < Ns) {
        cx[p] = s_pts[3 * j + 0];
        cy[p] = s_pts[3 * j + 1];
        cz[p] = s_pts[3 * j + 2];
      } else {
        cx[p] = cy[p] = cz[p] = 1e6f;   // shadow point -> zero influence
        jj[p] = 0;
      }
    }
    #pragma unroll
    for (int p = 0; p < 4; ++p) {
      const int n = nw + p;
      float qx = 0.f, qy = 0.f, qz = 0.f;
      if (n < N) {
        qx = q_pts[3 * n + 0];
        qy = q_pts[3 * n + 1];
        qz = q_pts[3 * n + 2];
      }
      sm.sP[wid][p][lane * 3 + 0] = cx[p] - qx;
      sm.sP[wid][p][lane * 3 + 1] = cy[p] - qy;
      sm.sP[wid][p][lane * 3 + 2] = cz[p] - qz;
      sm.sIdx[wid][p][lane] = jj[p];
    }
  } else if (lane < 28) {
    const int b = lane - H;
    #pragma unroll
    for (int p = 0; p < 4; ++p) {
      sm.sP[wid][p][78 + b * 3 + 0] = -1.0f;
      sm.sP[wid][p][78 + b * 3 + 1] = -1.0f;
      sm.sP[wid][p][78 + b * 3 + 2] = -1.0f;
    }
  }
  __syncwarp();

  // ── Phase 2 (batched): kp = gen_W @ p_vec + gen_b. ──
  if (lane < 30) {
    u64 aA[4] = {0, 0, 0, 0}, aB[4] = {0, 0, 0, 0};
    const u64* pp0 = reinterpret_cast<const u64*>(&sm.sP[wid][0][0]);
    const u64* pp1 = reinterpret_cast<const u64*>(&sm.sP[wid][1][0]);
    const u64* pp2 = reinterpret_cast<const u64*>(&sm.sP[wid][2][0]);
    const u64* pp3 = reinterpret_cast<const u64*>(&sm.sP[wid][3][0]);
    #pragma unroll 7
    for (int m2 = 0; m2 < 21; ++m2) {
      const u64 wA = sm.genWT2[m2 * 32 + lane];
      const u64 wB = sm.genWT2[(m2 + 21) * 32 + lane];
      aA[0] = ffma2(wA, pp0[m2], aA[0]);  aB[0] = ffma2(wB, pp0[m2 + 21], aB[0]);
      aA[1] = ffma2(wA, pp1[m2], aA[1]);  aB[1] = ffma2(wB, pp1[m2 + 21], aB[1]);
      aA[2] = ffma2(wA, pp2[m2], aA[2]);  aB[2] = ffma2(wB, pp2[m2 + 21], aB[2]);
      aA[3] = ffma2(wA, pp3[m2], aA[3]);  aB[3] = ffma2(wB, pp3[m2 + 21], aB[3]);
    }
    const float gb = sm.genB[lane];
    #pragma unroll
    for (int p = 0; p < 4; ++p) {
      const float2 ra = unpack2(aA[p]);
      const float2 rb = unpack2(aB[p]);
      sm.sKP[wid][p][lane] = (ra.x + ra.y) + (rb.x + rb.y) + gb;
    }
  }
  __syncwarp();

  const int half = lane >> 4;        // which point of the active pair
  const int cg   = lane & 15;        // column group: cols 4*cg .. 4*cg+3

  // ── Two point-pairs: (0,1) then (2,3). ──
  for (int pp = 0; pp < 2; ++pp) {
    __syncwarp();   // prior pair's swv reads complete before overwrite

    // Phase 3: influence weights for both points of the pair.
    #pragma unroll
    for (int pt = 0; pt < 2; ++pt) {
      const int p = 2 * pp + pt;
      for (int t = lane; t < KP * H; t += 32) {
        const int k = t / H;
        const int h = t - k * H;
        const float dx = sm.sP[wid][p][h * 3 + 0] - sm.sKP[wid][p][k * 3 + 0];
        const float dy = sm.sP[wid][p][h * 3 + 1] - sm.sKP[wid][p][k * 3 + 1];
        const float dz = sm.sP[wid][p][h * 3 + 2] - sm.sKP[wid][p][k * 3 + 2];
        const float d  = sqrtf(fmaf(dx, dx, fmaf(dy, dy, dz * dz)));
        sm.swv[wid][pt][h * 12 + k] = fmaxf(1.0f - d * INV_EXT, 0.0f);
      }
    }
    __syncwarp();

    // Phase 4 (paired): lane handles point (2*pp + half), cols 4cg..4cg+3.
    const int p = 2 * pp + half;
    const int n = nw + p;
    const int* idx = &sm.sIdx[wid][p][0];
    const float* wvp = &sm.swv[wid][half][0];

    u64 acc[5][4];   // [kk][c]: (k=2kk, k=2kk+1) for col 4cg+c
    #pragma unroll
    for (int kk = 0; kk < 5; ++kk)
      #pragma unroll
      for (int c = 0; c < 4; ++c) acc[kk][c] = 0;

    auto accum = [&](int h, u64 x8) {
      uint32_t ulo = (uint32_t)x8;
      uint32_t uhi = (uint32_t)(x8 >> 32);
      const float2 f01 = __half22float2(*reinterpret_cast<__half2*>(&ulo));
      const float2 f23 = __half22float2(*reinterpret_cast<__half2*>(&uhi));
      const u64 xc[4] = {pack2(f01.x, f01.x), pack2(f01.y, f01.y),
                         pack2(f23.x, f23.x), pack2(f23.y, f23.y)};
      const u64* wp = reinterpret_cast<const u64*>(wvp + h * 12);
      #pragma unroll
      for (int kk = 0; kk < 5; ++kk) {
        const u64 w2 = wp[kk];
        #pragma unroll
        for (int c = 0; c < 4; ++c)
          acc[kk][c] = ffma2(w2, xc[c], acc[kk][c]);
      }
    };

    // MLP-batched gathers: 9 / 9 / 8 rows in flight.
    u64 xb[9], xc2[9];
    #pragma unroll
    for (int hh = 0; hh < 9; ++hh)
      xb[hh] = *reinterpret_cast<const u64*>(
          g_X + (size_t)idx[hh] * CIN + 4 * cg);
    #pragma unroll
    for (int hh = 0; hh < 9; ++hh)
      xc2[hh] = *reinterpret_cast<const u64*>(
          g_X + (size_t)idx[9 + hh] * CIN + 4 * cg);
    #pragma unroll
    for (int hh = 0; hh < 9; ++hh) accum(hh, xb[hh]);
    #pragma unroll
    for (int hh = 0; hh < 8; ++hh)
      xb[hh] = *reinterpret_cast<const u64*>(
          g_X + (size_t)idx[18 + hh] * CIN + 4 * cg);
    #pragma unroll
    for (int hh = 0; hh < 9; ++hh) accum(9 + hh, xc2[hh]);
    #pragma unroll
    for (int hh = 0; hh < 8; ++hh) accum(18 + hh, xb[hh]);

    // Store: per k, 4 fp16 cols per lane -> one 8-B store (full 128-B row/k).
    if (n < N) {
      __half* base = g_A + (size_t)n * KDIM;
      #pragma unroll
      for (int kk = 0; kk < 5; ++kk) {
        const float2 v0 = unpack2(acc[kk][0]);   // col 4cg+0: (k even, k odd)
        const float2 v1 = unpack2(acc[kk][1]);
        const float2 v2 = unpack2(acc[kk][2]);
        const float2 v3 = unpack2(acc[kk][3]);
        const __half2 e01 = __floats2half2_rn(v0.x, v1.x);
        const __half2 e23 = __floats2half2_rn(v2.x, v3.x);
        const __half2 o01 = __floats2half2_rn(v0.y, v1.y);
        const __half2 o23 = __floats2half2_rn(v2.y, v3.y);
        u64 we = ((u64)*reinterpret_cast<const uint32_t*>(&e23) << 32) |
                 *reinterpret_cast<const uint32_t*>(&e01);
        u64 wo = ((u64)*reinterpret_cast<const uint32_t*>(&o23) << 32) |
                 *reinterpret_cast<const uint32_t*>(&o01);
        *reinterpret_cast<u64*>(base + (2 * kk) * CIN + 4 * cg) = we;
        *reinterpret_cast<u64*>(base + (2 * kk + 1) * CIN + 4 * cg) = wo;
      }
    }
  }
}

// ───────────────────── Kernel 2: fp16 mma.sync GEMM (round-12, verbatim) ────────

constexpr int KT      = 64;
constexpr int PITCH   = 144;
constexpr int TSZ     = 128 * PITCH;       // 18432 B
constexpr int STAGE   = 2 * TSZ;           // 36864 B
constexpr int NSTAGES = 3;
constexpr int GSMEM   = NSTAGES * STAGE;   // 110592 B
constexpr int NKT     = KDIM / KT;         // 10
constexpr int GNT     = 128;

__global__ void __launch_bounds__(GNT, 2)
gemm_kernel(float* __restrict__ out, int N)
{
  extern __shared__ char sm[];
  const uint32_t sb = smem_u32(sm);
  const int tid  = threadIdx.x;
  const int lane = tid & 31;
  const int wid  = tid >> 5;
  const int wr   = wid >> 1;
  const int wc   = wid & 1;
  const size_t n0 = (size_t)blockIdx.x * 128;

  auto load_stage = [&](int st, int kc) {
    const uint32_t base = sb + st * STAGE;
    #pragma unroll
    for (int i = 0; i < 8; ++i) {
      const int id = tid + i * GNT;
      const int r  = id >> 3;
      const int c  = id & 7;
      const uint32_t d = r * PITCH + c * 16;
      cp16(base + d,       g_A + (n0 + r) * KDIM + kc * KT + c * 8);
      cp16(base + TSZ + d, g_B + (size_t)r * KDIM + kc * KT + c * 8);
    }
  };

  load_stage(0, 0); cp_commit();
  load_stage(1, 1); cp_commit();

  const int arow  = lane & 15;
  const int acolB = (lane >> 4) * 16;
  const int brow  = (lane & 7) + ((lane >> 4) << 3);
  const int bcolB = ((lane >> 3) & 1) * 16;

  float acc[4][8][4];
  #pragma unroll
  for (int mi = 0; mi < 4; ++mi)
    #pragma unroll
    for (int ni = 0; ni < 8; ++ni)
      #pragma unroll
      for (int j = 0; j < 4; ++j) acc[mi][ni][j] = 0.f;

  for (int kc = 0; kc < NKT; ++kc) {
    const int st = kc % NSTAGES;
    cp_wait1();
    __syncthreads();

    if (kc + 2 < NKT) load_stage((kc + 2) % NSTAGES, kc + 2);
    cp_commit();

    const uint32_t tA = sb + st * STAGE;
    const uint32_t tB = sb + st * STAGE + TSZ;

    #pragma unroll
    for (int ks = 0; ks < 4; ++ks) {
      uint32_t ah[4][4], bh[8][2];
      #pragma unroll
      for (int mi = 0; mi < 4; ++mi) {
        const uint32_t ao =
            (wr * 64 + mi * 16 + arow) * PITCH + ks * 32 + acolB;
        ldm4(ah[mi], tA + ao);
      }
      #pragma unroll
      for (int bi = 0; bi < 4; ++bi) {
        const uint32_t bo =
            (wc * 64 + bi * 16 + brow) * PITCH + ks * 32 + bcolB;
        uint32_t t4[4];
        ldm4(t4, tB + bo);
        bh[2 * bi][0] = t4[0]; bh[2 * bi][1] = t4[1];
        bh[2 * bi + 1][0] = t4[2]; bh[2 * bi + 1][1] = t4[3];
      }
      #pragma unroll
      for (int mi = 0; mi < 4; ++mi)
        #pragma unroll
        for (int ni = 0; ni < 8; ++ni)
          mma16816(acc[mi][ni], ah[mi], bh[ni]);
    }
  }

  const int trow = lane >> 2;
  const int tcol = (lane & 3) * 2;
  #pragma unroll
  for (int mi = 0; mi < 4; ++mi) {
    const size_t row = n0 + wr * 64 + mi * 16 + trow;
    #pragma unroll
    for (int ni = 0; ni < 8; ++ni) {
      const int col = wc * 64 + ni * 8 + tcol;
      if (row < (size_t)N) {
        *reinterpret_cast<float2*>(out + row * COUT + col) =
            make_float2(acc[mi][ni][0], acc[mi][ni][1]);
        *reinterpret_cast<float2*>(out + (row + 8) * COUT + col) =
            make_float2(acc[mi][ni][2], acc[mi][ni][3]);
      }
    }
  }
}

}  // namespace

// ───────────────────────────── launch ─────────────────────────────

extern "C" void kernel_launch(void* const* d_in, const int* in_sizes, int n_in,
                              void* d_out, int out_size) {
  const float* q_pts = (const float*)d_in[0];
  const float* s_pts = (const float*)d_in[1];
  const float* x     = (const float*)d_in[2];
  const float* genW  = (const float*)d_in[3];
  const float* genB  = (const float*)d_in[4];
  const float* wts   = (const float*)d_in[5];
  const int*   inds  = (const int*)d_in[6];
  float* out = (float*)d_out;

  int N  = in_sizes[0] / 3;
  const int Ns = in_sizes[1] / 3;
  if (N > MAXN) N = MAXN;

  cudaFuncSetAttribute(gemm_kernel,
                       cudaFuncAttributeMaxDynamicSharedMemorySize, GSMEM);

  prep_kernel<<<1024, 256>>>(x, wts, N * CIN);

  const int grid1 = (N + TILE - 1) / TILE;
  producer_kernel<<<grid1, NT>>>(q_pts, s_pts, genW, genB, inds, N, Ns);

  const int grid3 = (N + 127) / 128;
  gemm_kernel<<<grid3, GNT, GSMEM>>>(out, N);
}